// round 13
// baseline (speedup 1.0000x reference)
#include <cuda_runtime.h>
#include <cuda_fp16.h>
#include <math.h>

#define NPTS 4096
#define NB   8
#define KNN  10
#define TPB  256
#define LOSS_BLOCKS 128        // 128 * 256 = 32768 = NB * NPTS
#define FULLMASK 0xFFFFFFFFu

// scratch: normals in original point order
__device__ float g_nrm[2][3][NB * NPTS];

// pair of points, half precision: {x0,x1},{y0,y1},{z0,z1}, pad -> 16B
struct Pair { __half2 x, y, z, pad; };

// monotone float -> ordered uint transform (preserves <), d2 >= 0 here
__device__ __forceinline__ unsigned fkey(float f) {
    unsigned b = __float_as_uint(f);
    unsigned m = (unsigned)((int)b >> 31) | 0x80000000u;
    return b ^ m;
}
__device__ __forceinline__ float ikey_pos(unsigned k) {
    return __uint_as_float(k ^ 0x80000000u);
}
// branch-free sorted-insert ripple of packed key into ascending a[0..9]
__device__ __forceinline__ void ripple(unsigned (&a)[KNN], unsigned k) {
#pragma unroll
    for (int r = 0; r < KNN; ++r) {
        unsigned lo = min(a[r], k);
        k = max(a[r], k);
        a[r] = lo;
    }
}

__global__ void __launch_bounds__(TPB, 3)
normals_kernel(const float* __restrict__ pred, const float* __restrict__ gt,
               float* __restrict__ out) {
    __shared__ Pair sh[NPTS / 2];   // 32 KB

    if (blockIdx.x == 0 && blockIdx.y == 0 && blockIdx.z == 0 && threadIdx.x == 0)
        out[0] = 0.0f;

    const int cloud = blockIdx.z;
    const int b     = blockIdx.y;
    const float* __restrict__ base =
        ((cloud == 0) ? pred : gt) + (size_t)b * 3 * NPTS;

    // cooperative load + fp16 pack (pair-interleaved)
    for (int t = threadIdx.x; t < NPTS / 2; t += TPB) {
        const int i0 = 2 * t;
        float x0 = base[i0],            x1 = base[i0 + 1];
        float y0 = base[NPTS + i0],     y1 = base[NPTS + i0 + 1];
        float z0 = base[2 * NPTS + i0], z1 = base[2 * NPTS + i0 + 1];
        Pair pr;
        pr.x   = __floats2half2_rn(x0, x1);
        pr.y   = __floats2half2_rn(y0, y1);
        pr.z   = __floats2half2_rn(z0, z1);
        pr.pad = __float2half2_rn(0.0f);
        sh[t] = pr;
    }
    __syncthreads();

    const int p = blockIdx.x * TPB + threadIdx.x;   // query point
    const float qx = base[p], qy = base[NPTS + p], qz = base[2 * NPTS + p];
    const __half2 qx2 = __float2half2_rn(qx);
    const __half2 qy2 = __float2half2_rn(qy);
    const __half2 qz2 = __float2half2_rn(qz);

    // ascending top-10 of packed keys (dist[31:12] | idx[11:0])
    unsigned a[KNN];
#pragma unroll
    for (int r = 0; r < KNN; ++r) a[r] = 0xFF7FF000u;  // fkey(FLT_MAX) & ~0xFFF
    float  thr   = 3.4e38f;
    __half thr_h = __ushort_as_half((unsigned short)0x7C00u);  // +inf

#define PDIST(P, d)                                                      \
    {                                                                    \
        __half2 dx = __hsub2((P).x, qx2);                                \
        __half2 dy = __hsub2((P).y, qy2);                                \
        __half2 dz = __hsub2((P).z, qz2);                                \
        d = __hfma2(dx, dx, __hfma2(dy, dy, __hmul2(dz, dz)));           \
    }
#define PAIREXP(dp, bi)                                                  \
    if (__hlt(__hmin(__low2half(dp), __high2half(dp)), thr_h)) {         \
        float f0 = __low2float(dp), f1 = __high2float(dp);               \
        if (f0 < thr) {                                                  \
            ripple(a, (fkey(f0) & 0xFFFFF000u) | (unsigned)(bi));        \
            thr = ikey_pos(a[KNN - 1] | 0xFFFu);                         \
            thr_h = __float2half_ru(thr);                                \
        }                                                                \
        if (f1 < thr) {                                                  \
            ripple(a, (fkey(f1) & 0xFFFFF000u) | (unsigned)((bi) + 1));  \
            thr = ikey_pos(a[KNN - 1] | 0xFFFu);                         \
            thr_h = __float2half_ru(thr);                                \
        }                                                                \
    }

    // scan 8 candidates (4 pairs) per iteration; all LDS are warp-broadcast
    for (int jp = 0; jp < NPTS / 2; jp += 4) {
        Pair P0 = sh[jp + 0];
        Pair P1 = sh[jp + 1];
        Pair P2 = sh[jp + 2];
        Pair P3 = sh[jp + 3];
        __half2 d0, d1, d2, d3;
        PDIST(P0, d0) PDIST(P1, d1) PDIST(P2, d2) PDIST(P3, d3)
        __half2 m2 = __hmin2(__hmin2(d0, d1), __hmin2(d2, d3));
        __half  mm = __hmin(__low2half(m2), __high2half(m2));
        if (__hlt(mm, thr_h)) {
            PAIREXP(d0, 2 * jp + 0)
            PAIREXP(d1, 2 * jp + 2)
            PAIREXP(d2, 2 * jp + 4)
            PAIREXP(d3, 2 * jp + 6)
        }
    }
#undef PDIST
#undef PAIREXP

    // ---- gather exact float coords of the 10 neighbors (q-centered) ----
    float nx[KNN], ny[KNN], nz[KNN];
#pragma unroll
    for (int r = 0; r < KNN; ++r) {
        int id = (int)(a[r] & 0xFFFu);
        nx[r] = base[id] - qx;
        ny[r] = base[NPTS + id] - qy;
        nz[r] = base[2 * NPTS + id] - qz;
    }
    float mx = 0.f, my = 0.f, mz = 0.f;
#pragma unroll
    for (int r = 0; r < KNN; ++r) { mx += nx[r]; my += ny[r]; mz += nz[r]; }
    const float invk = 1.0f / (float)KNN;
    mx *= invk; my *= invk; mz *= invk;

    float cxx = 0.f, cxy = 0.f, cxz = 0.f, cyy = 0.f, cyz = 0.f, czz = 0.f;
#pragma unroll
    for (int r = 0; r < KNN; ++r) {
        float dx = nx[r] - mx, dy = ny[r] - my, dz = nz[r] - mz;
        cxx = fmaf(dx, dx, cxx); cxy = fmaf(dx, dy, cxy); cxz = fmaf(dx, dz, cxz);
        cyy = fmaf(dy, dy, cyy); cyz = fmaf(dy, dz, cyz); czz = fmaf(dz, dz, czz);
    }

    // ---- analytic smallest-eigenvector of 3x3 symmetric (double) ----
    double a00 = (double)cxx * invk, a01 = (double)cxy * invk, a02 = (double)cxz * invk;
    double a11 = (double)cyy * invk, a12 = (double)cyz * invk, a22 = (double)czz * invk;
    double vx = 1.0, vy = 0.0, vz = 0.0;

    double tr3 = (a00 + a11 + a22) * (1.0 / 3.0);
    double b00 = a00 - tr3, b11 = a11 - tr3, b22 = a22 - tr3;
    double p2 = b00 * b00 + b11 * b11 + b22 * b22
              + 2.0 * (a01 * a01 + a02 * a02 + a12 * a12);
    if (p2 > 0.0) {
        double pp = sqrt(p2 * (1.0 / 6.0));
        double ip = 1.0 / pp;
        double db00 = b00 * ip, db11 = b11 * ip, db22 = b22 * ip;
        double da01 = a01 * ip, da02 = a02 * ip, da12 = a12 * ip;
        double halfdet = 0.5 * (db00 * (db11 * db22 - da12 * da12)
                              - da01 * (da01 * db22 - da12 * da02)
                              + da02 * (da01 * da12 - db11 * da02));
        halfdet = fmin(fmax(halfdet, -1.0), 1.0);
        double ang  = acos(halfdet) * (1.0 / 3.0);
        double lmin = tr3 + 2.0 * pp * cos(ang + 2.0943951023931953);

        double m00 = a00 - lmin, m11 = a11 - lmin, m22 = a22 - lmin;
        double c1x = a01 * a12 - a02 * m11, c1y = a02 * a01 - m00 * a12, c1z = m00 * m11 - a01 * a01;
        double c2x = a01 * m22 - a02 * a12, c2y = a02 * a02 - m00 * m22, c2z = m00 * a12 - a01 * a02;
        double c3x = m11 * m22 - a12 * a12, c3y = a12 * a02 - a01 * m22, c3z = a01 * a12 - m11 * a02;
        double n1 = c1x * c1x + c1y * c1y + c1z * c1z;
        double n2 = c2x * c2x + c2y * c2y + c2z * c2z;
        double n3 = c3x * c3x + c3y * c3y + c3z * c3z;
        double bx = c1x, by = c1y, bz = c1z, bn = n1;
        if (n2 > bn) { bx = c2x; by = c2y; bz = c2z; bn = n2; }
        if (n3 > bn) { bx = c3x; by = c3y; bz = c3z; bn = n3; }
        if (bn > 1e-100) {
            double si = 1.0 / sqrt(bn);
            vx = bx * si; vy = by * si; vz = bz * si;
        } else {
            double r0n = m00 * m00 + a01 * a01 + a02 * a02;
            double r1n = a01 * a01 + m11 * m11 + a12 * a12;
            double r2n = a02 * a02 + a12 * a12 + m22 * m22;
            double wx = m00, wy = a01, wz = a02, wn = r0n;
            if (r1n > wn) { wx = a01; wy = m11; wz = a12; wn = r1n; }
            if (r2n > wn) { wx = a02; wy = a12; wz = m22; wn = r2n; }
            if (wn > 1e-100) {
                double fx = fabs(wx), fy = fabs(wy), fz = fabs(wz);
                double ex = 0.0, ey = 0.0, ez = 0.0;
                if (fx <= fy && fx <= fz) ex = 1.0;
                else if (fy <= fz)        ey = 1.0;
                else                      ez = 1.0;
                double ux = wy * ez - wz * ey;
                double uy = wz * ex - wx * ez;
                double uz = wx * ey - wy * ex;
                double un = ux * ux + uy * uy + uz * uz;
                double si = 1.0 / sqrt(un);
                vx = ux * si; vy = uy * si; vz = uz * si;
            }
        }
    }

    const int gi = b * NPTS + p;
    g_nrm[cloud][0][gi] = (float)vx;
    g_nrm[cloud][1][gi] = (float)vy;
    g_nrm[cloud][2][gi] = (float)vz;
}

__global__ void loss_kernel(float* __restrict__ out) {
    __shared__ float wsum[TPB / 32];
    const int i = blockIdx.x * TPB + threadIdx.x;   // LOSS_BLOCKS*TPB == NB*NPTS
    float px = g_nrm[0][0][i], py = g_nrm[0][1][i], pz = g_nrm[0][2][i];
    float gx = g_nrm[1][0][i], gy = g_nrm[1][1][i], gz = g_nrm[1][2][i];
    float dot = px * gx + py * gy + pz * gz;
    float dn  = sqrtf(px * px + py * py + pz * pz)
              * sqrtf(gx * gx + gy * gy + gz * gz);
    float cs  = dot / fmaxf(dn, 1e-8f);
    float v   = 1.0f - fabsf(cs);
#pragma unroll
    for (int o = 16; o > 0; o >>= 1)
        v += __shfl_down_sync(FULLMASK, v, o);
    if ((threadIdx.x & 31) == 0) wsum[threadIdx.x >> 5] = v;
    __syncthreads();
    if (threadIdx.x < TPB / 32) {
        float b = wsum[threadIdx.x];
#pragma unroll
        for (int o = TPB / 64; o > 0; o >>= 1)
            b += __shfl_down_sync(0xFFu, b, o);
        if (threadIdx.x == 0)
            atomicAdd(out, b * (1.0f / (float)(NB * NPTS)));
    }
}

extern "C" void kernel_launch(void* const* d_in, const int* in_sizes, int n_in,
                              void* d_out, int out_size) {
    (void)in_sizes; (void)n_in; (void)out_size;
    const float* pred = (const float*)d_in[0];
    const float* gt   = (const float*)d_in[1];
    float* out = (float*)d_out;

    dim3 grid(NPTS / TPB, NB, 2);
    normals_kernel<<<grid, TPB>>>(pred, gt, out);
    loss_kernel<<<LOSS_BLOCKS, TPB>>>(out);
}

// round 14
// speedup vs baseline: 1.4450x; 1.4450x over previous
#include <cuda_runtime.h>
#include <math.h>

#define NPTS 4096
#define NB   8
#define KNN  10
#define TPB  256
#define LOSS_BLOCKS 128        // 128 * 256 = 32768 = NB * NPTS
#define SORT_TPB 256
#define PPT (NPTS / SORT_TPB)  // 16 points per sort thread
#define SBUK 4096              // 12-bit Morton buckets (16x16x16)
#define FULLMASK 0xFFFFFFFFu

// scratch: normals in ORIGINAL point order
__device__ float g_nrm[2][3][NB * NPTS];
// Morton-sorted clouds (x, y, z, |c|^2) + original indices
__device__ float4         g_sorted[2][NB][NPTS];
__device__ unsigned short g_sidx[2][NB][NPTS];

// monotone float -> ordered uint transform (preserves <)
__device__ __forceinline__ unsigned fkey(float f) {
    unsigned b = __float_as_uint(f);
    unsigned m = (unsigned)((int)b >> 31) | 0x80000000u;
    return b ^ m;
}
__device__ __forceinline__ float ikey_pos(unsigned k) {
    return __uint_as_float(k ^ 0x80000000u);
}
// branch-free sorted-insert ripple of packed key into ascending a[0..9]
__device__ __forceinline__ void ripple(unsigned (&a)[KNN], unsigned k) {
#pragma unroll
    for (int r = 0; r < KNN; ++r) {
        unsigned lo = min(a[r], k);
        k = max(a[r], k);
        a[r] = lo;
    }
}

__device__ __forceinline__ unsigned morton12(int cx, int cy, int cz) {
    unsigned m = 0;
#pragma unroll
    for (int k = 0; k < 4; ++k) {
        m |= (unsigned)(((cx >> k) & 1) << (3 * k))
           | (unsigned)(((cy >> k) & 1) << (3 * k + 1))
           | (unsigned)(((cz >> k) & 1) << (3 * k + 2));
    }
    return m;
}

// ---------------------------------------------------------------------------
// Morton counting sort of each (cloud, batch) into g_sorted / g_sidx
// ---------------------------------------------------------------------------
__global__ void sort_kernel(const float* __restrict__ pred,
                            const float* __restrict__ gt) {
    const int b     = blockIdx.x;
    const int cloud = blockIdx.y;
    const float* __restrict__ base =
        ((cloud == 0) ? pred : gt) + (size_t)b * 3 * NPTS;
    const int tid  = threadIdx.x;
    const int lane = tid & 31, w = tid >> 5;

    __shared__ unsigned cnt[SBUK];          // 16 KB bucket counters
    __shared__ unsigned tsum[SORT_TPB];
    __shared__ unsigned wtot[8];
    __shared__ float rmn[3][8], rmx[3][8];
    __shared__ float smin[3], sscl[3];

    for (int i = tid; i < SBUK; i += SORT_TPB) cnt[i] = 0;

    // per-axis min/max
    float mn[3] = {3.4e38f, 3.4e38f, 3.4e38f};
    float mx[3] = {-3.4e38f, -3.4e38f, -3.4e38f};
#pragma unroll
    for (int i = 0; i < PPT; ++i) {
        int idx = tid + i * SORT_TPB;
#pragma unroll
        for (int c = 0; c < 3; ++c) {
            float v = base[c * NPTS + idx];
            mn[c] = fminf(mn[c], v); mx[c] = fmaxf(mx[c], v);
        }
    }
#pragma unroll
    for (int o = 16; o > 0; o >>= 1)
#pragma unroll
        for (int c = 0; c < 3; ++c) {
            mn[c] = fminf(mn[c], __shfl_xor_sync(FULLMASK, mn[c], o));
            mx[c] = fmaxf(mx[c], __shfl_xor_sync(FULLMASK, mx[c], o));
        }
    if (lane == 0)
#pragma unroll
        for (int c = 0; c < 3; ++c) { rmn[c][w] = mn[c]; rmx[c][w] = mx[c]; }
    __syncthreads();
    if (tid == 0) {
#pragma unroll
        for (int c = 0; c < 3; ++c) {
            float a = rmn[c][0], z = rmx[c][0];
#pragma unroll
            for (int i = 1; i < 8; ++i) { a = fminf(a, rmn[c][i]); z = fmaxf(z, rmx[c][i]); }
            smin[c] = a;
            sscl[c] = 16.0f / fmaxf(z - a, 1e-20f);
        }
    }
    __syncthreads();
    const float x0 = smin[0], sx = sscl[0];
    const float y0 = smin[1], sy = sscl[1];
    const float z0 = smin[2], sz = sscl[2];

    int bk[PPT];
#pragma unroll
    for (int i = 0; i < PPT; ++i) {
        int idx = tid + i * SORT_TPB;
        float x = base[idx], y = base[NPTS + idx], z = base[2 * NPTS + idx];
        int cx = min(max((int)((x - x0) * sx), 0), 15);
        int cy = min(max((int)((y - y0) * sy), 0), 15);
        int cz = min(max((int)((z - z0) * sz), 0), 15);
        bk[i] = (int)morton12(cx, cy, cz);
        atomicAdd(&cnt[bk[i]], 1);
    }
    __syncthreads();

    // exclusive scan of 4096 bucket counts: 16 serial per thread + block scan
    unsigned loc[16];
    unsigned run = 0;
#pragma unroll
    for (int i = 0; i < 16; ++i) {
        loc[i] = run;
        run += cnt[tid * 16 + i];
    }
    tsum[tid] = run;
    __syncthreads();
    unsigned v = tsum[tid], incl = v;
#pragma unroll
    for (int o = 1; o < 32; o <<= 1) {
        unsigned t = __shfl_up_sync(FULLMASK, incl, o);
        if (lane >= o) incl += t;
    }
    if (lane == 31) wtot[w] = incl;
    __syncthreads();
    if (tid == 0) {
        unsigned r2 = 0;
#pragma unroll
        for (int i = 0; i < 8; ++i) { unsigned t = wtot[i]; wtot[i] = r2; r2 += t; }
    }
    __syncthreads();
    unsigned excl = incl - v + wtot[w];
    __syncthreads();
#pragma unroll
    for (int i = 0; i < 16; ++i) cnt[tid * 16 + i] = excl + loc[i];
    __syncthreads();

    // scatter (reload coords; L1/L2-hot)
#pragma unroll
    for (int i = 0; i < PPT; ++i) {
        int idx = tid + i * SORT_TPB;
        float x = base[idx], y = base[NPTS + idx], z = base[2 * NPTS + idx];
        unsigned slot = atomicAdd(&cnt[bk[i]], 1);
        g_sorted[cloud][b][slot] = make_float4(x, y, z, fmaf(x, x, fmaf(y, y, z * z)));
        g_sidx[cloud][b][slot]   = (unsigned short)idx;
    }
}

// ---------------------------------------------------------------------------
// brute-force KNN over Morton-ordered queries (warp-coherent inserts)
// ---------------------------------------------------------------------------
__global__ void __launch_bounds__(TPB, 2)
normals_kernel(float* __restrict__ out) {
    extern __shared__ float4 s[];   // 4096 sorted points = 64 KB

    if (blockIdx.x == 0 && blockIdx.y == 0 && blockIdx.z == 0 && threadIdx.x == 0)
        out[0] = 0.0f;

    const int cloud = blockIdx.z;
    const int b     = blockIdx.y;

    for (int t = threadIdx.x; t < NPTS; t += TPB)
        s[t] = g_sorted[cloud][b][t];
    __syncthreads();

    const int p = blockIdx.x * TPB + threadIdx.x;   // Morton-sorted position
    const float4 q = s[p];
    const float ax = -2.0f * q.x, ay = -2.0f * q.y, az = -2.0f * q.z;
    const float qw = q.w;

    unsigned a[KNN];
#pragma unroll
    for (int r = 0; r < KNN; ++r) a[r] = 0xFF7F0000u;  // huge finite-key init
    float thr = 3.4e38f;

    // true d2 = |c|^2 + |q|^2 - 2 q.c, folded into one fma chain
    for (int j = 0; j < NPTS; j += 4) {
        float4 c0 = s[j + 0];
        float4 c1 = s[j + 1];
        float4 c2 = s[j + 2];
        float4 c3 = s[j + 3];
        float d0 = fmaf(ax, c0.x, fmaf(ay, c0.y, fmaf(az, c0.z, c0.w + qw)));
        float d1 = fmaf(ax, c1.x, fmaf(ay, c1.y, fmaf(az, c1.z, c1.w + qw)));
        float d2 = fmaf(ax, c2.x, fmaf(ay, c2.y, fmaf(az, c2.z, c2.w + qw)));
        float d3 = fmaf(ax, c3.x, fmaf(ay, c3.y, fmaf(az, c3.z, c3.w + qw)));
        float m = fminf(fminf(d0, d1), fminf(d2, d3));
        if (m < thr) {
            if (d0 < thr) {
                ripple(a, (fkey(d0) & 0xFFFFF000u) | (unsigned)(j + 0));
                thr = ikey_pos(a[KNN - 1] | 0xFFFu);
            }
            if (d1 < thr) {
                ripple(a, (fkey(d1) & 0xFFFFF000u) | (unsigned)(j + 1));
                thr = ikey_pos(a[KNN - 1] | 0xFFFu);
            }
            if (d2 < thr) {
                ripple(a, (fkey(d2) & 0xFFFFF000u) | (unsigned)(j + 2));
                thr = ikey_pos(a[KNN - 1] | 0xFFFu);
            }
            if (d3 < thr) {
                ripple(a, (fkey(d3) & 0xFFFFF000u) | (unsigned)(j + 3));
                thr = ikey_pos(a[KNN - 1] | 0xFFFu);
            }
        }
    }

    // ---- local covariance of the 10 neighbors (centered on q) ----
    float mx = 0.f, my = 0.f, mz = 0.f;
#pragma unroll
    for (int r = 0; r < KNN; ++r) {
        float4 c = s[a[r] & 0xFFFu];
        mx += c.x - q.x; my += c.y - q.y; mz += c.z - q.z;
    }
    const float invk = 1.0f / (float)KNN;
    mx *= invk; my *= invk; mz *= invk;

    float cxx = 0.f, cxy = 0.f, cxz = 0.f, cyy = 0.f, cyz = 0.f, czz = 0.f;
#pragma unroll
    for (int r = 0; r < KNN; ++r) {
        float4 c = s[a[r] & 0xFFFu];
        float dx = (c.x - q.x) - mx;
        float dy = (c.y - q.y) - my;
        float dz = (c.z - q.z) - mz;
        cxx = fmaf(dx, dx, cxx); cxy = fmaf(dx, dy, cxy); cxz = fmaf(dx, dz, cxz);
        cyy = fmaf(dy, dy, cyy); cyz = fmaf(dy, dz, cyz); czz = fmaf(dz, dz, czz);
    }

    // ---- analytic smallest-eigenvector of 3x3 symmetric (double) ----
    double a00 = (double)cxx * invk, a01 = (double)cxy * invk, a02 = (double)cxz * invk;
    double a11 = (double)cyy * invk, a12 = (double)cyz * invk, a22 = (double)czz * invk;
    double vx = 1.0, vy = 0.0, vz = 0.0;

    double tr3 = (a00 + a11 + a22) * (1.0 / 3.0);
    double b00 = a00 - tr3, b11 = a11 - tr3, b22 = a22 - tr3;
    double p2 = b00 * b00 + b11 * b11 + b22 * b22
              + 2.0 * (a01 * a01 + a02 * a02 + a12 * a12);
    if (p2 > 0.0) {
        double pp = sqrt(p2 * (1.0 / 6.0));
        double ip = 1.0 / pp;
        double db00 = b00 * ip, db11 = b11 * ip, db22 = b22 * ip;
        double da01 = a01 * ip, da02 = a02 * ip, da12 = a12 * ip;
        double halfdet = 0.5 * (db00 * (db11 * db22 - da12 * da12)
                              - da01 * (da01 * db22 - da12 * da02)
                              + da02 * (da01 * da12 - db11 * da02));
        halfdet = fmin(fmax(halfdet, -1.0), 1.0);
        double ang  = acos(halfdet) * (1.0 / 3.0);
        double lmin = tr3 + 2.0 * pp * cos(ang + 2.0943951023931953);

        double m00 = a00 - lmin, m11 = a11 - lmin, m22 = a22 - lmin;
        double c1x = a01 * a12 - a02 * m11, c1y = a02 * a01 - m00 * a12, c1z = m00 * m11 - a01 * a01;
        double c2x = a01 * m22 - a02 * a12, c2y = a02 * a02 - m00 * m22, c2z = m00 * a12 - a01 * a02;
        double c3x = m11 * m22 - a12 * a12, c3y = a12 * a02 - a01 * m22, c3z = a01 * a12 - m11 * a02;
        double n1 = c1x * c1x + c1y * c1y + c1z * c1z;
        double n2 = c2x * c2x + c2y * c2y + c2z * c2z;
        double n3 = c3x * c3x + c3y * c3y + c3z * c3z;
        double bx = c1x, by = c1y, bz = c1z, bn = n1;
        if (n2 > bn) { bx = c2x; by = c2y; bz = c2z; bn = n2; }
        if (n3 > bn) { bx = c3x; by = c3y; bz = c3z; bn = n3; }
        if (bn > 1e-100) {
            double si = 1.0 / sqrt(bn);
            vx = bx * si; vy = by * si; vz = bz * si;
        } else {
            double r0n = m00 * m00 + a01 * a01 + a02 * a02;
            double r1n = a01 * a01 + m11 * m11 + a12 * a12;
            double r2n = a02 * a02 + a12 * a12 + m22 * m22;
            double wx = m00, wy = a01, wz = a02, wn = r0n;
            if (r1n > wn) { wx = a01; wy = m11; wz = a12; wn = r1n; }
            if (r2n > wn) { wx = a02; wy = a12; wz = m22; wn = r2n; }
            if (wn > 1e-100) {
                double fx = fabs(wx), fy = fabs(wy), fz = fabs(wz);
                double ex = 0.0, ey = 0.0, ez = 0.0;
                if (fx <= fy && fx <= fz) ex = 1.0;
                else if (fy <= fz)        ey = 1.0;
                else                      ez = 1.0;
                double ux = wy * ez - wz * ey;
                double uy = wz * ex - wx * ez;
                double uz = wx * ey - wy * ex;
                double un = ux * ux + uy * uy + uz * uz;
                double si = 1.0 / sqrt(un);
                vx = ux * si; vy = uy * si; vz = uz * si;
            }
        }
    }

    // scatter back to ORIGINAL point order so pred/gt pairing is preserved
    const int orig = (int)g_sidx[cloud][b][p];
    const int gi = b * NPTS + orig;
    g_nrm[cloud][0][gi] = (float)vx;
    g_nrm[cloud][1][gi] = (float)vy;
    g_nrm[cloud][2][gi] = (float)vz;
}

__global__ void loss_kernel(float* __restrict__ out) {
    __shared__ float wsum[TPB / 32];
    const int i = blockIdx.x * TPB + threadIdx.x;   // LOSS_BLOCKS*TPB == NB*NPTS
    float px = g_nrm[0][0][i], py = g_nrm[0][1][i], pz = g_nrm[0][2][i];
    float gx = g_nrm[1][0][i], gy = g_nrm[1][1][i], gz = g_nrm[1][2][i];
    float dot = px * gx + py * gy + pz * gz;
    float dn  = sqrtf(px * px + py * py + pz * pz)
              * sqrtf(gx * gx + gy * gy + gz * gz);
    float cs  = dot / fmaxf(dn, 1e-8f);
    float v   = 1.0f - fabsf(cs);
#pragma unroll
    for (int o = 16; o > 0; o >>= 1)
        v += __shfl_down_sync(FULLMASK, v, o);
    if ((threadIdx.x & 31) == 0) wsum[threadIdx.x >> 5] = v;
    __syncthreads();
    if (threadIdx.x < TPB / 32) {
        float b = wsum[threadIdx.x];
#pragma unroll
        for (int o = TPB / 64; o > 0; o >>= 1)
            b += __shfl_down_sync(0xFFu, b, o);
        if (threadIdx.x == 0)
            atomicAdd(out, b * (1.0f / (float)(NB * NPTS)));
    }
}

extern "C" void kernel_launch(void* const* d_in, const int* in_sizes, int n_in,
                              void* d_out, int out_size) {
    (void)in_sizes; (void)n_in; (void)out_size;
    const float* pred = (const float*)d_in[0];
    const float* gt   = (const float*)d_in[1];
    float* out = (float*)d_out;

    static bool attr_done = false;
    const int smem = NPTS * (int)sizeof(float4);   // 64 KB
    if (!attr_done) {
        cudaFuncSetAttribute(normals_kernel,
                             cudaFuncAttributeMaxDynamicSharedMemorySize, smem);
        attr_done = true;
    }

    sort_kernel<<<dim3(NB, 2), SORT_TPB>>>(pred, gt);
    dim3 grid(NPTS / TPB, NB, 2);
    normals_kernel<<<grid, TPB, smem>>>(out);
    loss_kernel<<<LOSS_BLOCKS, TPB>>>(out);
}

// round 16
// speedup vs baseline: 2.2532x; 1.5594x over previous
#include <cuda_runtime.h>
#include <math.h>

#define NPTS 4096
#define NB   8
#define KNN  10
#define TPB  256
#define LOSS_BLOCKS 128        // 128 * 256 = 32768 = NB * NPTS
#define SORT_TPB 256
#define PPT (NPTS / SORT_TPB)  // 16 points per sort thread
#define SBUK 4096              // 12-bit Morton buckets (16x16x16)
#define FULLMASK 0xFFFFFFFFu

// scratch: normals in ORIGINAL point order
__device__ float g_nrm[2][3][NB * NPTS];
// Morton-sorted queries (x, y, z, |c|^2) + original indices
__device__ float4         g_sorted[2][NB][NPTS];
__device__ unsigned short g_sidx[2][NB][NPTS];

// monotone float -> ordered uint transform (preserves <)
__device__ __forceinline__ unsigned fkey(float f) {
    unsigned b = __float_as_uint(f);
    unsigned m = (unsigned)((int)b >> 31) | 0x80000000u;
    return b ^ m;
}
__device__ __forceinline__ float ikey_pos(unsigned k) {
    return __uint_as_float(k ^ 0x80000000u);
}
// branch-free sorted-insert ripple of packed key into ascending a[0..9]
__device__ __forceinline__ void ripple(unsigned (&a)[KNN], unsigned k) {
#pragma unroll
    for (int r = 0; r < KNN; ++r) {
        unsigned lo = min(a[r], k);
        k = max(a[r], k);
        a[r] = lo;
    }
}

__device__ __forceinline__ unsigned morton12(int cx, int cy, int cz) {
    unsigned m = 0;
#pragma unroll
    for (int k = 0; k < 4; ++k) {
        m |= (unsigned)(((cx >> k) & 1) << (3 * k))
           | (unsigned)(((cy >> k) & 1) << (3 * k + 1))
           | (unsigned)(((cz >> k) & 1) << (3 * k + 2));
    }
    return m;
}

// ---------------------------------------------------------------------------
// Morton counting sort of each (cloud, batch) into g_sorted / g_sidx
// (defines the QUERY ordering only; candidates stay in original order)
// ---------------------------------------------------------------------------
__global__ void sort_kernel(const float* __restrict__ pred,
                            const float* __restrict__ gt) {
    const int b     = blockIdx.x;
    const int cloud = blockIdx.y;
    const float* __restrict__ base =
        ((cloud == 0) ? pred : gt) + (size_t)b * 3 * NPTS;
    const int tid  = threadIdx.x;
    const int lane = tid & 31, w = tid >> 5;

    __shared__ unsigned cnt[SBUK];          // 16 KB bucket counters
    __shared__ unsigned tsum[SORT_TPB];
    __shared__ unsigned wtot[8];
    __shared__ float rmn[3][8], rmx[3][8];
    __shared__ float smin[3], sscl[3];

    for (int i = tid; i < SBUK; i += SORT_TPB) cnt[i] = 0;

    // per-axis min/max
    float mn[3] = {3.4e38f, 3.4e38f, 3.4e38f};
    float mx[3] = {-3.4e38f, -3.4e38f, -3.4e38f};
#pragma unroll
    for (int i = 0; i < PPT; ++i) {
        int idx = tid + i * SORT_TPB;
#pragma unroll
        for (int c = 0; c < 3; ++c) {
            float v = base[c * NPTS + idx];
            mn[c] = fminf(mn[c], v); mx[c] = fmaxf(mx[c], v);
        }
    }
#pragma unroll
    for (int o = 16; o > 0; o >>= 1)
#pragma unroll
        for (int c = 0; c < 3; ++c) {
            mn[c] = fminf(mn[c], __shfl_xor_sync(FULLMASK, mn[c], o));
            mx[c] = fmaxf(mx[c], __shfl_xor_sync(FULLMASK, mx[c], o));
        }
    if (lane == 0)
#pragma unroll
        for (int c = 0; c < 3; ++c) { rmn[c][w] = mn[c]; rmx[c][w] = mx[c]; }
    __syncthreads();
    if (tid == 0) {
#pragma unroll
        for (int c = 0; c < 3; ++c) {
            float a = rmn[c][0], z = rmx[c][0];
#pragma unroll
            for (int i = 1; i < 8; ++i) { a = fminf(a, rmn[c][i]); z = fmaxf(z, rmx[c][i]); }
            smin[c] = a;
            sscl[c] = 16.0f / fmaxf(z - a, 1e-20f);
        }
    }
    __syncthreads();
    const float x0 = smin[0], sx = sscl[0];
    const float y0 = smin[1], sy = sscl[1];
    const float z0 = smin[2], sz = sscl[2];

    int bk[PPT];
#pragma unroll
    for (int i = 0; i < PPT; ++i) {
        int idx = tid + i * SORT_TPB;
        float x = base[idx], y = base[NPTS + idx], z = base[2 * NPTS + idx];
        int cx = min(max((int)((x - x0) * sx), 0), 15);
        int cy = min(max((int)((y - y0) * sy), 0), 15);
        int cz = min(max((int)((z - z0) * sz), 0), 15);
        bk[i] = (int)morton12(cx, cy, cz);
        atomicAdd(&cnt[bk[i]], 1);
    }
    __syncthreads();

    // exclusive scan of 4096 bucket counts: 16 serial per thread + block scan
    unsigned loc[16];
    unsigned run = 0;
#pragma unroll
    for (int i = 0; i < 16; ++i) {
        loc[i] = run;
        run += cnt[tid * 16 + i];
    }
    tsum[tid] = run;
    __syncthreads();
    unsigned v = tsum[tid], incl = v;
#pragma unroll
    for (int o = 1; o < 32; o <<= 1) {
        unsigned t = __shfl_up_sync(FULLMASK, incl, o);
        if (lane >= o) incl += t;
    }
    if (lane == 31) wtot[w] = incl;
    __syncthreads();
    if (tid == 0) {
        unsigned r2 = 0;
#pragma unroll
        for (int i = 0; i < 8; ++i) { unsigned t = wtot[i]; wtot[i] = r2; r2 += t; }
    }
    __syncthreads();
    unsigned excl = incl - v + wtot[w];
    __syncthreads();
#pragma unroll
    for (int i = 0; i < 16; ++i) cnt[tid * 16 + i] = excl + loc[i];
    __syncthreads();

    // scatter (reload coords; L1/L2-hot)
#pragma unroll
    for (int i = 0; i < PPT; ++i) {
        int idx = tid + i * SORT_TPB;
        float x = base[idx], y = base[NPTS + idx], z = base[2 * NPTS + idx];
        unsigned slot = atomicAdd(&cnt[bk[i]], 1);
        g_sorted[cloud][b][slot] = make_float4(x, y, z, fmaf(x, x, fmaf(y, y, z * z)));
        g_sidx[cloud][b][slot]   = (unsigned short)idx;
    }
}

// ---------------------------------------------------------------------------
// brute-force KNN: Morton-coherent queries, ORIGINAL-order candidate scan
// ---------------------------------------------------------------------------
__global__ void __launch_bounds__(TPB, 2)
normals_kernel(const float* __restrict__ pred, const float* __restrict__ gt,
               float* __restrict__ out) {
    extern __shared__ float4 s[];   // 4096 candidates (original order) = 64 KB

    if (blockIdx.x == 0 && blockIdx.y == 0 && blockIdx.z == 0 && threadIdx.x == 0)
        out[0] = 0.0f;

    const int cloud = blockIdx.z;
    const int b     = blockIdx.y;
    const float* __restrict__ base =
        ((cloud == 0) ? pred : gt) + (size_t)b * 3 * NPTS;

    // candidates in ORIGINAL order (random -> fast threshold convergence)
    for (int t = threadIdx.x; t < NPTS; t += TPB) {
        float x = base[t];
        float y = base[NPTS + t];
        float z = base[2 * NPTS + t];
        s[t] = make_float4(x, y, z, fmaf(x, x, fmaf(y, y, z * z)));
    }
    __syncthreads();

    // query taken from the Morton-sorted permutation -> warp-coherent lanes
    const int p = blockIdx.x * TPB + threadIdx.x;
    const float4 q = g_sorted[cloud][b][p];
    const float ax = -2.0f * q.x, ay = -2.0f * q.y, az = -2.0f * q.z;
    const float qw = q.w;

    unsigned a[KNN];
#pragma unroll
    for (int r = 0; r < KNN; ++r) a[r] = 0xFF7F0000u;  // huge finite-key init
    float thr = 3.4e38f;

    // true d2 = |c|^2 + |q|^2 - 2 q.c, folded into one fma chain
    for (int j = 0; j < NPTS; j += 4) {
        float4 c0 = s[j + 0];
        float4 c1 = s[j + 1];
        float4 c2 = s[j + 2];
        float4 c3 = s[j + 3];
        float d0 = fmaf(ax, c0.x, fmaf(ay, c0.y, fmaf(az, c0.z, c0.w + qw)));
        float d1 = fmaf(ax, c1.x, fmaf(ay, c1.y, fmaf(az, c1.z, c1.w + qw)));
        float d2 = fmaf(ax, c2.x, fmaf(ay, c2.y, fmaf(az, c2.z, c2.w + qw)));
        float d3 = fmaf(ax, c3.x, fmaf(ay, c3.y, fmaf(az, c3.z, c3.w + qw)));
        float m = fminf(fminf(d0, d1), fminf(d2, d3));
        if (m < thr) {
            if (d0 < thr) {
                ripple(a, (fkey(d0) & 0xFFFFF000u) | (unsigned)(j + 0));
                thr = ikey_pos(a[KNN - 1] | 0xFFFu);
            }
            if (d1 < thr) {
                ripple(a, (fkey(d1) & 0xFFFFF000u) | (unsigned)(j + 1));
                thr = ikey_pos(a[KNN - 1] | 0xFFFu);
            }
            if (d2 < thr) {
                ripple(a, (fkey(d2) & 0xFFFFF000u) | (unsigned)(j + 2));
                thr = ikey_pos(a[KNN - 1] | 0xFFFu);
            }
            if (d3 < thr) {
                ripple(a, (fkey(d3) & 0xFFFFF000u) | (unsigned)(j + 3));
                thr = ikey_pos(a[KNN - 1] | 0xFFFu);
            }
        }
    }

    // ---- local covariance of the 10 neighbors (centered on q) ----
    float mx = 0.f, my = 0.f, mz = 0.f;
#pragma unroll
    for (int r = 0; r < KNN; ++r) {
        float4 c = s[a[r] & 0xFFFu];
        mx += c.x - q.x; my += c.y - q.y; mz += c.z - q.z;
    }
    const float invk = 1.0f / (float)KNN;
    mx *= invk; my *= invk; mz *= invk;

    float cxx = 0.f, cxy = 0.f, cxz = 0.f, cyy = 0.f, cyz = 0.f, czz = 0.f;
#pragma unroll
    for (int r = 0; r < KNN; ++r) {
        float4 c = s[a[r] & 0xFFFu];
        float dx = (c.x - q.x) - mx;
        float dy = (c.y - q.y) - my;
        float dz = (c.z - q.z) - mz;
        cxx = fmaf(dx, dx, cxx); cxy = fmaf(dx, dy, cxy); cxz = fmaf(dx, dz, cxz);
        cyy = fmaf(dy, dy, cyy); cyz = fmaf(dy, dz, cyz); czz = fmaf(dz, dz, czz);
    }

    // ---- analytic smallest-eigenvector of 3x3 symmetric (double) ----
    double a00 = (double)cxx * invk, a01 = (double)cxy * invk, a02 = (double)cxz * invk;
    double a11 = (double)cyy * invk, a12 = (double)cyz * invk, a22 = (double)czz * invk;
    double vx = 1.0, vy = 0.0, vz = 0.0;

    double tr3 = (a00 + a11 + a22) * (1.0 / 3.0);
    double b00 = a00 - tr3, b11 = a11 - tr3, b22 = a22 - tr3;
    double p2 = b00 * b00 + b11 * b11 + b22 * b22
              + 2.0 * (a01 * a01 + a02 * a02 + a12 * a12);
    if (p2 > 0.0) {
        double pp = sqrt(p2 * (1.0 / 6.0));
        double ip = 1.0 / pp;
        double db00 = b00 * ip, db11 = b11 * ip, db22 = b22 * ip;
        double da01 = a01 * ip, da02 = a02 * ip, da12 = a12 * ip;
        double halfdet = 0.5 * (db00 * (db11 * db22 - da12 * da12)
                              - da01 * (da01 * db22 - da12 * da02)
                              + da02 * (da01 * da12 - db11 * da02));
        halfdet = fmin(fmax(halfdet, -1.0), 1.0);
        double ang  = acos(halfdet) * (1.0 / 3.0);
        double lmin = tr3 + 2.0 * pp * cos(ang + 2.0943951023931953);

        double m00 = a00 - lmin, m11 = a11 - lmin, m22 = a22 - lmin;
        double c1x = a01 * a12 - a02 * m11, c1y = a02 * a01 - m00 * a12, c1z = m00 * m11 - a01 * a01;
        double c2x = a01 * m22 - a02 * a12, c2y = a02 * a02 - m00 * m22, c2z = m00 * a12 - a01 * a02;
        double c3x = m11 * m22 - a12 * a12, c3y = a12 * a02 - a01 * m22, c3z = a01 * a12 - m11 * a02;
        double n1 = c1x * c1x + c1y * c1y + c1z * c1z;
        double n2 = c2x * c2x + c2y * c2y + c2z * c2z;
        double n3 = c3x * c3x + c3y * c3y + c3z * c3z;
        double bx = c1x, by = c1y, bz = c1z, bn = n1;
        if (n2 > bn) { bx = c2x; by = c2y; bz = c2z; bn = n2; }
        if (n3 > bn) { bx = c3x; by = c3y; bz = c3z; bn = n3; }
        if (bn > 1e-100) {
            double si = 1.0 / sqrt(bn);
            vx = bx * si; vy = by * si; vz = bz * si;
        } else {
            double r0n = m00 * m00 + a01 * a01 + a02 * a02;
            double r1n = a01 * a01 + m11 * m11 + a12 * a12;
            double r2n = a02 * a02 + a12 * a12 + m22 * m22;
            double wx = m00, wy = a01, wz = a02, wn = r0n;
            if (r1n > wn) { wx = a01; wy = m11; wz = a12; wn = r1n; }
            if (r2n > wn) { wx = a02; wy = a12; wz = m22; wn = r2n; }
            if (wn > 1e-100) {
                double fx = fabs(wx), fy = fabs(wy), fz = fabs(wz);
                double ex = 0.0, ey = 0.0, ez = 0.0;
                if (fx <= fy && fx <= fz) ex = 1.0;
                else if (fy <= fz)        ey = 1.0;
                else                      ez = 1.0;
                double ux = wy * ez - wz * ey;
                double uy = wz * ex - wx * ez;
                double uz = wx * ey - wy * ex;
                double un = ux * ux + uy * uy + uz * uz;
                double si = 1.0 / sqrt(un);
                vx = ux * si; vy = uy * si; vz = uz * si;
            }
        }
    }

    // scatter back to ORIGINAL point order so pred/gt pairing is preserved
    const int orig = (int)g_sidx[cloud][b][p];
    const int gi = b * NPTS + orig;
    g_nrm[cloud][0][gi] = (float)vx;
    g_nrm[cloud][1][gi] = (float)vy;
    g_nrm[cloud][2][gi] = (float)vz;
}

__global__ void loss_kernel(float* __restrict__ out) {
    __shared__ float wsum[TPB / 32];
    const int i = blockIdx.x * TPB + threadIdx.x;   // LOSS_BLOCKS*TPB == NB*NPTS
    float px = g_nrm[0][0][i], py = g_nrm[0][1][i], pz = g_nrm[0][2][i];
    float gx = g_nrm[1][0][i], gy = g_nrm[1][1][i], gz = g_nrm[1][2][i];
    float dot = px * gx + py * gy + pz * gz;
    float dn  = sqrtf(px * px + py * py + pz * pz)
              * sqrtf(gx * gx + gy * gy + gz * gz);
    float cs  = dot / fmaxf(dn, 1e-8f);
    float v   = 1.0f - fabsf(cs);
#pragma unroll
    for (int o = 16; o > 0; o >>= 1)
        v += __shfl_down_sync(FULLMASK, v, o);
    if ((threadIdx.x & 31) == 0) wsum[threadIdx.x >> 5] = v;
    __syncthreads();
    if (threadIdx.x < TPB / 32) {
        float b = wsum[threadIdx.x];
#pragma unroll
        for (int o = TPB / 64; o > 0; o >>= 1)
            b += __shfl_down_sync(0xFFu, b, o);
        if (threadIdx.x == 0)
            atomicAdd(out, b * (1.0f / (float)(NB * NPTS)));
    }
}

extern "C" void kernel_launch(void* const* d_in, const int* in_sizes, int n_in,
                              void* d_out, int out_size) {
    (void)in_sizes; (void)n_in; (void)out_size;
    const float* pred = (const float*)d_in[0];
    const float* gt   = (const float*)d_in[1];
    float* out = (float*)d_out;

    static bool attr_done = false;
    const int smem = NPTS * (int)sizeof(float4);   // 64 KB
    if (!attr_done) {
        cudaFuncSetAttribute(normals_kernel,
                             cudaFuncAttributeMaxDynamicSharedMemorySize, smem);
        attr_done = true;
    }

    sort_kernel<<<dim3(NB, 2), SORT_TPB>>>(pred, gt);
    dim3 grid(NPTS / TPB, NB, 2);
    normals_kernel<<<grid, TPB, smem>>>(pred, gt, out);
    loss_kernel<<<LOSS_BLOCKS, TPB>>>(out);
}